// round 3
// baseline (speedup 1.0000x reference)
#include <cuda_runtime.h>
#include <math.h>

#define B_ 4
#define N_ 2048
#define VD_ 256
#define CD_ 64
#define H_ 4
#define D_ 64
#define ROWS_ (B_*N_)          // 8192

// ---------------- scratch (device globals; no allocation) ----------------
// offsets in floats
#define OFF_VN    ((size_t)0)            // 8192*256
#define OFF_CN    ((size_t)2097152)      // 8192*64
#define OFF_QKV   ((size_t)2621440)      // 8192*512
#define OFF_QKC   ((size_t)6815744)      // 8192*512
#define OFF_VV    ((size_t)11010048)     // 8192*256
#define OFF_VC    ((size_t)13107200)     // 8192*256
#define OFF_Q     ((size_t)15204352)     // 16*2048*128
#define OFF_K     ((size_t)19398656)
#define OFF_VCAT  ((size_t)23592960)
#define OFF_OV    ((size_t)27787264)     // 8192*256
#define OFF_OC    ((size_t)29884416)     // 8192*256
#define SCRATCH_FLOATS ((size_t)31981568)

__device__ __align__(16) float g_scratch[SCRATCH_FLOATS];

// ---------------- block reduction ----------------
__device__ __forceinline__ float block_sum(float v, float* red) {
    int lane = threadIdx.x & 31;
    #pragma unroll
    for (int o = 16; o; o >>= 1) v += __shfl_xor_sync(0xffffffffu, v, o);
    if (lane == 0) red[threadIdx.x >> 5] = v;
    __syncthreads();
    int nw = (blockDim.x + 31) >> 5;
    float r = (lane < nw) ? red[lane] : 0.f;
    #pragma unroll
    for (int o = 16; o; o >>= 1) r += __shfl_xor_sync(0xffffffffu, r, o);
    __syncthreads();  // protect red for a following call
    return r;
}

// ---------------- layernorm (blockDim == dim) ----------------
__global__ void ln_kernel(const float* __restrict__ x, const float* __restrict__ g,
                          const float* __restrict__ b, float* __restrict__ y, int dim)
{
    __shared__ float red[32];
    size_t row = blockIdx.x;
    float v = x[row * dim + threadIdx.x];
    float mean = block_sum(v, red) / (float)dim;
    float dv = v - mean;
    float var = block_sum(dv * dv, red) / (float)dim;
    y[row * dim + threadIdx.x] = dv * rsqrtf(var + 1e-5f) * g[threadIdx.x] + b[threadIdx.x];
}

// ---------------- generic GEMM: C = A[MxK] @ W[KxN] + bias ----------------
// 64x64 tile, K-step 16, 256 threads, 4x4 per thread
__global__ void gemm_bias(const float* __restrict__ A, const float* __restrict__ W,
                          const float* __restrict__ bias, float* __restrict__ Cm,
                          int M, int Nc, int K)
{
    __shared__ __align__(16) float As[16 * 68];  // [k][m], padded
    __shared__ __align__(16) float Bs[16 * 64];  // [k][n]
    const int tid = threadIdx.x;
    const int tx = tid & 15, ty = tid >> 4;
    const int m0 = blockIdx.y * 64;
    const int n0 = blockIdx.x * 64;
    float acc[4][4] = {};
    for (int k0 = 0; k0 < K; k0 += 16) {
        #pragma unroll
        for (int i = tid; i < 1024; i += 256) {
            int k = i & 15, m = i >> 4;
            As[k * 68 + m] = A[(size_t)(m0 + m) * K + k0 + k];
        }
        #pragma unroll
        for (int i = tid; i < 1024; i += 256) {
            int n = i & 63, k = i >> 6;
            Bs[k * 64 + n] = W[(size_t)(k0 + k) * Nc + n0 + n];
        }
        __syncthreads();
        #pragma unroll
        for (int k = 0; k < 16; k++) {
            float4 av = *(const float4*)&As[k * 68 + ty * 4];
            float4 bv = *(const float4*)&Bs[k * 64 + tx * 4];
            float a[4] = {av.x, av.y, av.z, av.w};
            float b4[4] = {bv.x, bv.y, bv.z, bv.w};
            #pragma unroll
            for (int ii = 0; ii < 4; ii++)
                #pragma unroll
                for (int jj = 0; jj < 4; jj++)
                    acc[ii][jj] += a[ii] * b4[jj];
        }
        __syncthreads();
    }
    #pragma unroll
    for (int ii = 0; ii < 4; ii++) {
        int m = m0 + ty * 4 + ii;
        int n = n0 + tx * 4;
        float4 out;
        out.x = acc[ii][0] + bias[n + 0];
        out.y = acc[ii][1] + bias[n + 1];
        out.z = acc[ii][2] + bias[n + 2];
        out.w = acc[ii][3] + bias[n + 3];
        *(float4*)&Cm[(size_t)m * Nc + n] = out;
    }
}

// ---------------- RMS norm + head scatter into Qcat/Kcat/Vcat ----------------
__global__ void rms_scatter(const float* __restrict__ QKv, const float* __restrict__ QKc,
                            const float* __restrict__ Vv, const float* __restrict__ Vc,
                            const float* __restrict__ rms_v, const float* __restrict__ rms_c,
                            float* __restrict__ Qc, float* __restrict__ Kc, float* __restrict__ Vcat)
{
    __shared__ float red[32];
    int row = blockIdx.x;
    int b = row / N_, n = row % N_;
    int t = threadIdx.x;  // 256
    const float* qv = QKv + (size_t)row * 512;
    const float* qc = QKc + (size_t)row * 512;
    float sv = 0.f, sc = 0.f;
    #pragma unroll
    for (int i = t; i < 512; i += 256) { float a = qv[i]; sv += a * a; float c = qc[i]; sc += c * c; }
    sv = block_sum(sv, red);
    sc = block_sum(sc, red);
    float iv = rsqrtf(sv / 512.f + 1e-6f);
    float ic = rsqrtf(sc / 512.f + 1e-6f);
    int h = t >> 6, d = t & 63;
    size_t base = ((size_t)(b * H_ + h) * N_ + n) * 128;
    int q = h * 64 + d;
    Qc[base + d]        = qv[q]       * iv * rms_v[q];
    Qc[base + 64 + d]   = qc[q]       * ic * rms_c[q];
    Kc[base + d]        = qv[256 + q] * iv * rms_v[256 + q];
    Kc[base + 64 + d]   = qc[256 + q] * ic * rms_c[256 + q];
    Vcat[base + d]      = Vv[(size_t)row * 256 + q];
    Vcat[base + 64 + d] = Vc[(size_t)row * 256 + q];
}

// ---------------- flash attention, d=128, BM=BN=64 ----------------
#define QS 68   // padded stride for d-major Q/K tiles
#define FA_SMEM_FLOATS (128*QS*2 + 64*128 + 64*64 + 192)
#define FA_SMEM_BYTES  (FA_SMEM_FLOATS*4)

__global__ void flash_kernel(const float* __restrict__ Q, const float* __restrict__ K,
                             const float* __restrict__ Vp, float* __restrict__ OV,
                             float* __restrict__ OC)
{
    extern __shared__ __align__(16) float sm[];
    float* Qs   = sm;                 // [128][QS]  (d-major)
    float* Ks   = Qs + 128 * QS;      // [128][QS]
    float* Vs   = Ks + 128 * QS;      // [64][128]  (j-major)
    float* Ps   = Vs + 64 * 128;      // [64][64]   (i-major)
    float* m_sh = Ps + 64 * 64;
    float* l_sh = m_sh + 64;
    float* a_sh = l_sh + 64;

    const int tid = threadIdx.x;
    const int tx = tid & 15;   // S: j-cols/4 ; PV: d-cols/8
    const int ty = tid >> 4;   // i-rows/4 (same in both phases)
    const int bh = blockIdx.y;
    const int i0 = blockIdx.x * 64;
    const size_t base = (size_t)bh * N_ * 128;

    for (int idx = tid; idx < 64 * 128; idx += 256) {
        int i = idx >> 7, d = idx & 127;
        Qs[d * QS + i] = Q[base + (size_t)(i0 + i) * 128 + d];
    }
    if (tid < 64) { m_sh[tid] = -3e38f; l_sh[tid] = 0.f; }
    float o[4][8];
    #pragma unroll
    for (int i = 0; i < 4; i++)
        #pragma unroll
        for (int j = 0; j < 8; j++) o[i][j] = 0.f;
    __syncthreads();

    for (int j0 = 0; j0 < N_; j0 += 64) {
        for (int idx = tid; idx < 64 * 128; idx += 256) {
            int j = idx >> 7, d = idx & 127;
            float kv = K[base + (size_t)(j0 + j) * 128 + d];
            Ks[d * QS + j] = kv;
            Vs[idx] = Vp[base + (size_t)(j0 + j) * 128 + d];
        }
        __syncthreads();

        float s[4][4] = {};
        #pragma unroll 4
        for (int d = 0; d < 128; d++) {
            float4 av = *(const float4*)&Qs[d * QS + ty * 4];
            float4 bv = *(const float4*)&Ks[d * QS + tx * 4];
            float a[4] = {av.x, av.y, av.z, av.w};
            float b4[4] = {bv.x, bv.y, bv.z, bv.w};
            #pragma unroll
            for (int ii = 0; ii < 4; ii++)
                #pragma unroll
                for (int jj = 0; jj < 4; jj++)
                    s[ii][jj] += a[ii] * b4[jj];
        }
        #pragma unroll
        for (int ii = 0; ii < 4; ii++)
            #pragma unroll
            for (int jj = 0; jj < 4; jj++) s[ii][jj] *= 0.125f;  // 1/sqrt(64)

        #pragma unroll
        for (int ii = 0; ii < 4; ii++) {
            int r = ty * 4 + ii;
            float mloc = fmaxf(fmaxf(s[ii][0], s[ii][1]), fmaxf(s[ii][2], s[ii][3]));
            #pragma unroll
            for (int off = 8; off; off >>= 1)
                mloc = fmaxf(mloc, __shfl_xor_sync(0xffffffffu, mloc, off));
            float mold = m_sh[r];
            float mnew = fmaxf(mold, mloc);
            float p0 = __expf(s[ii][0] - mnew);
            float p1 = __expf(s[ii][1] - mnew);
            float p2 = __expf(s[ii][2] - mnew);
            float p3 = __expf(s[ii][3] - mnew);
            float ls = p0 + p1 + p2 + p3;
            #pragma unroll
            for (int off = 8; off; off >>= 1)
                ls += __shfl_xor_sync(0xffffffffu, ls, off);
            if (tx == 0) {
                float alpha = __expf(mold - mnew);
                m_sh[r] = mnew;
                l_sh[r] = l_sh[r] * alpha + ls;
                a_sh[r] = alpha;
            }
            float4 pv = make_float4(p0, p1, p2, p3);
            *(float4*)&Ps[r * 64 + tx * 4] = pv;
        }
        __syncthreads();

        float alpha[4];
        #pragma unroll
        for (int ii = 0; ii < 4; ii++) alpha[ii] = a_sh[ty * 4 + ii];
        #pragma unroll
        for (int ii = 0; ii < 4; ii++)
            #pragma unroll
            for (int dd = 0; dd < 8; dd++) o[ii][dd] *= alpha[ii];

        #pragma unroll 2
        for (int j = 0; j < 64; j++) {
            float4 v0 = *(const float4*)&Vs[j * 128 + tx * 8];
            float4 v1 = *(const float4*)&Vs[j * 128 + tx * 8 + 4];
            float vv[8] = {v0.x, v0.y, v0.z, v0.w, v1.x, v1.y, v1.z, v1.w};
            #pragma unroll
            for (int ii = 0; ii < 4; ii++) {
                float pr = Ps[(ty * 4 + ii) * 64 + j];
                #pragma unroll
                for (int dd = 0; dd < 8; dd++) o[ii][dd] += pr * vv[dd];
            }
        }
        __syncthreads();
    }

    const int b = bh / H_, h = bh % H_;
    #pragma unroll
    for (int ii = 0; ii < 4; ii++) {
        float invl = 1.f / l_sh[ty * 4 + ii];
        int n = i0 + ty * 4 + ii;
        size_t rowbase = ((size_t)b * N_ + n) * 256 + h * 64;
        #pragma unroll
        for (int dd = 0; dd < 8; dd++) {
            int d = tx * 8 + dd;
            float val = o[ii][dd] * invl;
            if (d < 64) OV[rowbase + d] = val;
            else        OC[rowbase + (d - 64)] = val;
        }
    }
}

// ---------------- launch ----------------
extern "C" void kernel_launch(void* const* d_in, const int* in_sizes, int n_in,
                              void* d_out, int out_size)
{
    (void)in_sizes; (void)n_in; (void)out_size;
    const float* V     = (const float*)d_in[0];
    const float* C     = (const float*)d_in[1];
    const float* vn_g  = (const float*)d_in[2];
    const float* vn_b  = (const float*)d_in[3];
    const float* cn_g  = (const float*)d_in[4];
    const float* cn_b  = (const float*)d_in[5];
    const float* W_vqk = (const float*)d_in[6];
    const float* b_vqk = (const float*)d_in[7];
    const float* rms_v = (const float*)d_in[8];
    const float* W_cqk = (const float*)d_in[9];
    const float* b_cqk = (const float*)d_in[10];
    const float* rms_c = (const float*)d_in[11];
    const float* W_vv  = (const float*)d_in[12];
    const float* b_vv  = (const float*)d_in[13];
    const float* W_cv  = (const float*)d_in[14];
    const float* b_cv  = (const float*)d_in[15];
    const float* W_ov  = (const float*)d_in[16];
    const float* b_ov  = (const float*)d_in[17];
    const float* W_oc  = (const float*)d_in[18];
    const float* b_oc  = (const float*)d_in[19];

    float* out_v = (float*)d_out;                       // (B,N,VD)
    float* out_c = out_v + (size_t)B_ * N_ * VD_;       // (B,N,CD)

    float* S = nullptr;
    cudaGetSymbolAddress((void**)&S, g_scratch);
    float* Vn   = S + OFF_VN;
    float* Cn   = S + OFF_CN;
    float* QKv  = S + OFF_QKV;
    float* QKc  = S + OFF_QKC;
    float* Vv   = S + OFF_VV;
    float* Vc   = S + OFF_VC;
    float* Qcat = S + OFF_Q;
    float* Kcat = S + OFF_K;
    float* Vcat = S + OFF_VCAT;
    float* OV   = S + OFF_OV;
    float* OC   = S + OFF_OC;

    cudaFuncSetAttribute(flash_kernel, cudaFuncAttributeMaxDynamicSharedMemorySize, FA_SMEM_BYTES);

    // 1. layernorms
    ln_kernel<<<ROWS_, VD_>>>(V, vn_g, vn_b, Vn, VD_);
    ln_kernel<<<ROWS_, CD_>>>(C, cn_g, cn_b, Cn, CD_);

    // 2. projections
    gemm_bias<<<dim3(8, 128), 256>>>(Vn, W_vqk, b_vqk, QKv, ROWS_, 512, 256);
    gemm_bias<<<dim3(4, 128), 256>>>(Vn, W_vv,  b_vv,  Vv,  ROWS_, 256, 256);
    gemm_bias<<<dim3(8, 128), 256>>>(Cn, W_cqk, b_cqk, QKc, ROWS_, 512, 64);
    gemm_bias<<<dim3(4, 128), 256>>>(Cn, W_cv,  b_cv,  Vc,  ROWS_, 256, 64);

    // 3. rms norm + head-split scatter into concatenated Q/K/V (d=128)
    rms_scatter<<<ROWS_, 256>>>(QKv, QKc, Vv, Vc, rms_v, rms_c, Qcat, Kcat, Vcat);

    // 4. fused dual-stream flash attention
    flash_kernel<<<dim3(N_ / 64, B_ * H_), 256, FA_SMEM_BYTES>>>(Qcat, Kcat, Vcat, OV, OC);

    // 5. output projections
    gemm_bias<<<dim3(4, 128), 256>>>(OV, W_ov, b_ov, out_v, ROWS_, VD_, 256);
    gemm_bias<<<dim3(1, 128), 256>>>(OC, W_oc, b_oc, out_c, ROWS_, CD_, 256);
}

// round 11
// speedup vs baseline: 3.2796x; 3.2796x over previous
#include <cuda_runtime.h>
#include <cuda_bf16.h>
#include <cuda_fp16.h>
#include <math.h>
#include <stdint.h>

#define B_ 4
#define N_ 2048
#define VD_ 256
#define CD_ 64
#define H_ 4
#define ROWS_ (B_*N_)          // 8192
#define BH_ (B_*H_)            // 16

// ---------------- scratch (device global; no allocation) ----------------
#define OFF_VN    ((size_t)0)
#define OFF_CN    ((size_t)2097152)
#define OFF_QKV   ((size_t)2621440)
#define OFF_QKC   ((size_t)6815744)
#define OFF_VV    ((size_t)11010048)
#define OFF_VC    ((size_t)13107200)
#define OFF_OV    ((size_t)15204352)
#define OFF_OC    ((size_t)17301504)
#define OFF_S     ((size_t)19398656)    // 16*2048*2048 fp32
#define OFF_PB    ((size_t)86507520)    // 16*2048*2048 fp16
#define OFF_QHI   ((size_t)120061952)
#define OFF_QLO   ((size_t)122159104)
#define OFF_KHI   ((size_t)124256256)
#define OFF_KLO   ((size_t)126353408)
#define OFF_VT    ((size_t)128450560)
#define SCRATCH_FLOATS ((size_t)130547712)

__device__ __align__(1024) float g_scratch[SCRATCH_FLOATS];

// ================= warp MMA helpers (arch-agnostic: ldmatrix + mma.sync) =============
__device__ __forceinline__ uint32_t smem_u32(const void* p) {
    uint32_t a;
    asm("{ .reg .u64 t; cvta.to.shared.u64 t, %1; cvt.u32.u64 %0, t; }" : "=r"(a) : "l"(p));
    return a;
}
__device__ __forceinline__ void ldsm4(uint32_t& r0, uint32_t& r1, uint32_t& r2, uint32_t& r3,
                                      uint32_t addr) {
    asm volatile("ldmatrix.sync.aligned.m8n8.x4.shared.b16 {%0,%1,%2,%3}, [%4];"
                 : "=r"(r0), "=r"(r1), "=r"(r2), "=r"(r3) : "r"(addr));
}
__device__ __forceinline__ void mma_bf16(float* c, const uint32_t* a, const uint32_t* b) {
    asm volatile(
        "mma.sync.aligned.m16n8k16.row.col.f32.bf16.bf16.f32 "
        "{%0,%1,%2,%3}, {%4,%5,%6,%7}, {%8,%9}, {%0,%1,%2,%3};"
        : "+f"(c[0]), "+f"(c[1]), "+f"(c[2]), "+f"(c[3])
        : "r"(a[0]), "r"(a[1]), "r"(a[2]), "r"(a[3]), "r"(b[0]), "r"(b[1]));
}
__device__ __forceinline__ void mma_fp16(float* c, const uint32_t* a, const uint32_t* b) {
    asm volatile(
        "mma.sync.aligned.m16n8k16.row.col.f32.f16.f16.f32 "
        "{%0,%1,%2,%3}, {%4,%5,%6,%7}, {%8,%9}, {%0,%1,%2,%3};"
        : "+f"(c[0]), "+f"(c[1]), "+f"(c[2]), "+f"(c[3])
        : "r"(a[0]), "r"(a[1]), "r"(a[2]), "r"(a[3]), "r"(b[0]), "r"(b[1]));
}

// tile: 128 rows x 128 x 16-bit (256B/row), 16B chunks XOR-swizzled within the row
__device__ __forceinline__ uint32_t tile_off(int r, int c16) {
    return (uint32_t)(r * 256 + ((c16 ^ (r & 7)) << 4));
}
// 256-thread cooperative load of a [128 x 128] 16-bit tile (row stride in elements)
template <typename T>
__device__ __forceinline__ void load_tile(char* dst, const T* src, size_t stride, int tid) {
    #pragma unroll
    for (int it = 0; it < 8; it++) {
        int idx = tid + it * 256;
        int r = idx >> 4, c = idx & 15;
        uint4 v = *(const uint4*)(src + (size_t)r * stride + c * 8);
        *(uint4*)(dst + tile_off(r, c)) = v;
    }
}

// per-warp 32x64 MMA over one [128x128] A tile and [128x128] B tile (both k-major)
// accumulates into c[2][8][4]. FP16 selects the f16 MMA, else bf16.
template <bool FP16>
__device__ __forceinline__ void warp_mma_128(float (*c)[8][4], uint32_t Abase, uint32_t Bbase,
                                             int m0, int n0, int lane) {
    const int j = lane & 7, g = lane >> 3;
    #pragma unroll
    for (int k = 0; k < 8; k++) {
        uint32_t a[2][4];
        #pragma unroll
        for (int mi = 0; mi < 2; mi++) {
            int arow = m0 + mi * 16 + ((g & 1) ? 8 : 0) + j;
            int akc = k * 2 + (g >> 1);
            ldsm4(a[mi][0], a[mi][1], a[mi][2], a[mi][3], Abase + tile_off(arow, akc));
        }
        uint32_t b[8][2];
        #pragma unroll
        for (int nb = 0; nb < 4; nb++) {
            int brow = n0 + nb * 16 + (g >> 1) * 8 + j;
            int bkc = k * 2 + (g & 1);
            ldsm4(b[nb * 2][0], b[nb * 2][1], b[nb * 2 + 1][0], b[nb * 2 + 1][1],
                  Bbase + tile_off(brow, bkc));
        }
        #pragma unroll
        for (int mi = 0; mi < 2; mi++)
            #pragma unroll
            for (int ni = 0; ni < 8; ni++) {
                if (FP16) mma_fp16(c[mi][ni], a[mi], b[ni]);
                else      mma_bf16(c[mi][ni], a[mi], b[ni]);
            }
    }
}

// ---------------- block reductions ----------------
__device__ __forceinline__ float block_sum(float v, float* red) {
    int lane = threadIdx.x & 31;
    #pragma unroll
    for (int o = 16; o; o >>= 1) v += __shfl_xor_sync(0xffffffffu, v, o);
    if (lane == 0) red[threadIdx.x >> 5] = v;
    __syncthreads();
    int nw = (blockDim.x + 31) >> 5;
    float r = (lane < nw) ? red[lane] : 0.f;
    #pragma unroll
    for (int o = 16; o; o >>= 1) r += __shfl_xor_sync(0xffffffffu, r, o);
    __syncthreads();
    return r;
}
__device__ __forceinline__ float block_max(float v, float* red) {
    int lane = threadIdx.x & 31;
    #pragma unroll
    for (int o = 16; o; o >>= 1) v = fmaxf(v, __shfl_xor_sync(0xffffffffu, v, o));
    if (lane == 0) red[threadIdx.x >> 5] = v;
    __syncthreads();
    int nw = (blockDim.x + 31) >> 5;
    float r = (lane < nw) ? red[lane] : -3.0e38f;
    #pragma unroll
    for (int o = 16; o; o >>= 1) r = fmaxf(r, __shfl_xor_sync(0xffffffffu, r, o));
    __syncthreads();
    return r;
}

// ---------------- layernorm ----------------
__global__ void ln_kernel(const float* __restrict__ x, const float* __restrict__ g,
                          const float* __restrict__ b, float* __restrict__ y, int dim)
{
    __shared__ float red[32];
    size_t row = blockIdx.x;
    float v = x[row * dim + threadIdx.x];
    float mean = block_sum(v, red) / (float)dim;
    float dv = v - mean;
    float var = block_sum(dv * dv, red) / (float)dim;
    y[row * dim + threadIdx.x] = dv * rsqrtf(var + 1e-5f) * g[threadIdx.x] + b[threadIdx.x];
}

// ---------------- fp32 GEMM (projections) ----------------
__global__ void gemm_bias(const float* __restrict__ A, const float* __restrict__ W,
                          const float* __restrict__ bias, float* __restrict__ Cm,
                          int M, int Nc, int K)
{
    __shared__ __align__(16) float As[16 * 68];
    __shared__ __align__(16) float Bs[16 * 64];
    const int tid = threadIdx.x;
    const int tx = tid & 15, ty = tid >> 4;
    const int m0 = blockIdx.y * 64;
    const int n0 = blockIdx.x * 64;
    float acc[4][4] = {};
    for (int k0 = 0; k0 < K; k0 += 16) {
        #pragma unroll
        for (int i = tid; i < 1024; i += 256) {
            int k = i & 15, m = i >> 4;
            As[k * 68 + m] = A[(size_t)(m0 + m) * K + k0 + k];
        }
        #pragma unroll
        for (int i = tid; i < 1024; i += 256) {
            int n = i & 63, k = i >> 6;
            Bs[k * 64 + n] = W[(size_t)(k0 + k) * Nc + n0 + n];
        }
        __syncthreads();
        #pragma unroll
        for (int k = 0; k < 16; k++) {
            float4 av = *(const float4*)&As[k * 68 + ty * 4];
            float4 bv = *(const float4*)&Bs[k * 64 + tx * 4];
            float a[4] = {av.x, av.y, av.z, av.w};
            float b4[4] = {bv.x, bv.y, bv.z, bv.w};
            #pragma unroll
            for (int ii = 0; ii < 4; ii++)
                #pragma unroll
                for (int jj = 0; jj < 4; jj++)
                    acc[ii][jj] += a[ii] * b4[jj];
        }
        __syncthreads();
    }
    #pragma unroll
    for (int ii = 0; ii < 4; ii++) {
        int m = m0 + ty * 4 + ii;
        int n = n0 + tx * 4;
        float4 out;
        out.x = acc[ii][0] + bias[n + 0];
        out.y = acc[ii][1] + bias[n + 1];
        out.z = acc[ii][2] + bias[n + 2];
        out.w = acc[ii][3] + bias[n + 3];
        *(float4*)&Cm[(size_t)m * Nc + n] = out;
    }
}

// ---------------- RMS norm + hi/lo bf16 split + head scatter ----------------
__device__ __forceinline__ void split_bf16(float x, __nv_bfloat16& hi, __nv_bfloat16& lo) {
    hi = __float2bfloat16(x);
    lo = __float2bfloat16(x - __bfloat162float(hi));
}

__global__ void rms_scatter(const float* __restrict__ QKv, const float* __restrict__ QKc,
                            const float* __restrict__ Vv, const float* __restrict__ Vc,
                            const float* __restrict__ rms_v, const float* __restrict__ rms_c,
                            __nv_bfloat16* __restrict__ Qhi, __nv_bfloat16* __restrict__ Qlo,
                            __nv_bfloat16* __restrict__ Khi, __nv_bfloat16* __restrict__ Klo,
                            __half* __restrict__ Vt)
{
    __shared__ float red[32];
    int row = blockIdx.x;
    int b = row / N_, n = row % N_;
    int t = threadIdx.x;  // 256
    const float* qv = QKv + (size_t)row * 512;
    const float* qc = QKc + (size_t)row * 512;
    float sv = 0.f, sc = 0.f;
    #pragma unroll
    for (int i = t; i < 512; i += 256) { float a = qv[i]; sv += a * a; float c = qc[i]; sc += c * c; }
    sv = block_sum(sv, red);
    sc = block_sum(sc, red);
    float iv = rsqrtf(sv / 512.f + 1e-6f);
    float ic = rsqrtf(sc / 512.f + 1e-6f);
    int h = t >> 6, d = t & 63;
    int q = t;
    size_t bh = (size_t)(b * H_ + h);
    size_t qbase = (bh * N_ + n) * 128;

    float qV = qv[q] * iv * rms_v[q];
    float qC = qc[q] * ic * rms_c[q];
    float kV = qv[256 + q] * iv * rms_v[256 + q];
    float kC = qc[256 + q] * ic * rms_c[256 + q];

    __nv_bfloat16 hi, lo;
    split_bf16(qV, hi, lo); Qhi[qbase + d] = hi;      Qlo[qbase + d] = lo;
    split_bf16(qC, hi, lo); Qhi[qbase + 64 + d] = hi; Qlo[qbase + 64 + d] = lo;
    split_bf16(kV, hi, lo); Khi[qbase + d] = hi;      Klo[qbase + d] = lo;
    split_bf16(kC, hi, lo); Khi[qbase + 64 + d] = hi; Klo[qbase + 64 + d] = lo;

    // V transposed: Vt[bh][d][j], fp16
    Vt[(bh * 128 + d) * N_ + n]      = __float2half(Vv[(size_t)row * 256 + q]);
    Vt[(bh * 128 + 64 + d) * N_ + n] = __float2half(Vc[(size_t)row * 256 + q]);
}

// ---------------- GEMM1: S = (Qh.Kh^T + Qh.Kl^T + Ql.Kh^T) / 8 ----------------
#define SC1_SMEM (4 * 32768)

__global__ void __launch_bounds__(256, 1)
scores_kernel(const __nv_bfloat16* __restrict__ Qh, const __nv_bfloat16* __restrict__ Ql,
              const __nv_bfloat16* __restrict__ Kh, const __nv_bfloat16* __restrict__ Kl,
              float* __restrict__ S)
{
    extern __shared__ __align__(16) char sm[];
    char* Ah = sm;
    char* Al = sm + 32768;
    char* Bh = sm + 65536;
    char* Bl = sm + 98304;

    const int tid = threadIdx.x, wid = tid >> 5, lane = tid & 31;
    const int jt = blockIdx.x, it = blockIdx.y, bh = blockIdx.z;
    const size_t qoff = ((size_t)bh * N_ + it * 128) * 128;
    const size_t koff = ((size_t)bh * N_ + jt * 128) * 128;

    load_tile(Ah, Qh + qoff, 128, tid);
    load_tile(Al, Ql + qoff, 128, tid);
    load_tile(Bh, Kh + koff, 128, tid);
    load_tile(Bl, Kl + koff, 128, tid);
    __syncthreads();

    const int m0 = (wid & 3) * 32;
    const int n0 = (wid >> 2) * 64;
    float c[2][8][4] = {};

    warp_mma_128<false>(c, smem_u32(Ah), smem_u32(Bh), m0, n0, lane);
    warp_mma_128<false>(c, smem_u32(Ah), smem_u32(Bl), m0, n0, lane);
    warp_mma_128<false>(c, smem_u32(Al), smem_u32(Bh), m0, n0, lane);

    const int qr = lane >> 2, qc2 = (lane & 3) * 2;
    float* Sbase = S + (size_t)bh * N_ * N_;
    #pragma unroll
    for (int mi = 0; mi < 2; mi++) {
        #pragma unroll
        for (int ni = 0; ni < 8; ni++) {
            int row = it * 128 + m0 + mi * 16 + qr;
            int col = jt * 128 + n0 + ni * 8 + qc2;
            float2 lo = make_float2(c[mi][ni][0] * 0.125f, c[mi][ni][1] * 0.125f);
            float2 hi = make_float2(c[mi][ni][2] * 0.125f, c[mi][ni][3] * 0.125f);
            *(float2*)(Sbase + (size_t)row * N_ + col)       = lo;
            *(float2*)(Sbase + (size_t)(row + 8) * N_ + col) = hi;
        }
    }
}

// ---------------- softmax: P(fp16) = softmax(S) rowwise ----------------
__global__ void softmax_kernel(const float* __restrict__ S, __half* __restrict__ P)
{
    __shared__ float red[32];
    size_t row = blockIdx.x;
    const float* s = S + row * N_;
    int t = threadIdx.x;  // 256
    float v[8];
    float mx = -3.0e38f;
    #pragma unroll
    for (int g = 0; g < 2; g++) {
        float4 x = *(const float4*)(s + g * 1024 + t * 4);
        v[g * 4 + 0] = x.x; v[g * 4 + 1] = x.y; v[g * 4 + 2] = x.z; v[g * 4 + 3] = x.w;
        mx = fmaxf(mx, fmaxf(fmaxf(x.x, x.y), fmaxf(x.z, x.w)));
    }
    mx = block_max(mx, red);
    float lsum = 0.f;
    #pragma unroll
    for (int i = 0; i < 8; i++) { v[i] = __expf(v[i] - mx); lsum += v[i]; }
    float inv = 1.f / block_sum(lsum, red);
    __half* p = P + row * N_;
    #pragma unroll
    for (int g = 0; g < 2; g++) {
        int base = g * 1024 + t * 4;
        __half2 a, b;
        a.x = __float2half(v[g * 4 + 0] * inv);
        a.y = __float2half(v[g * 4 + 1] * inv);
        b.x = __float2half(v[g * 4 + 2] * inv);
        b.y = __float2half(v[g * 4 + 3] * inv);
        *(__half2*)(p + base)     = a;
        *(__half2*)(p + base + 2) = b;
    }
}

// ---------------- GEMM2: O = P @ Vt^T (fp16), scatter into OV/OC ----------------
#define SC2_SMEM (2 * 32768)

__global__ void __launch_bounds__(256, 1)
pv_kernel(const __half* __restrict__ P, const __half* __restrict__ Vt,
          float* __restrict__ OV, float* __restrict__ OC)
{
    extern __shared__ __align__(16) char sm[];
    char* Ta = sm;
    char* Tb = sm + 32768;

    const int tid = threadIdx.x, wid = tid >> 5, lane = tid & 31;
    const int it = blockIdx.x, bh = blockIdx.y;

    const __half* prow = P + ((size_t)bh * N_ + it * 128) * N_;
    const __half* vrow = Vt + (size_t)bh * 128 * N_;

    const int m0 = (wid & 3) * 32;
    const int n0 = (wid >> 2) * 64;
    float c[2][8][4] = {};

    for (int ch = 0; ch < 16; ch++) {
        load_tile(Ta, prow + ch * 128, N_, tid);
        load_tile(Tb, vrow + ch * 128, N_, tid);
        __syncthreads();
        warp_mma_128<true>(c, smem_u32(Ta), smem_u32(Tb), m0, n0, lane);
        __syncthreads();
    }

    const int qr = lane >> 2, qc2 = (lane & 3) * 2;
    const int b = bh >> 2, h = bh & 3;
    #pragma unroll
    for (int mi = 0; mi < 2; mi++) {
        #pragma unroll
        for (int ni = 0; ni < 8; ni++) {
            int d = n0 + ni * 8 + qc2;
            float* dst = (d < 64) ? OV : OC;
            int dc = d & 63;
            int n1 = it * 128 + m0 + mi * 16 + qr;
            size_t r1 = ((size_t)b * N_ + n1) * 256 + h * 64 + dc;
            size_t r2 = ((size_t)b * N_ + n1 + 8) * 256 + h * 64 + dc;
            *(float2*)(dst + r1) = make_float2(c[mi][ni][0], c[mi][ni][1]);
            *(float2*)(dst + r2) = make_float2(c[mi][ni][2], c[mi][ni][3]);
        }
    }
}

// ---------------- launch ----------------
extern "C" void kernel_launch(void* const* d_in, const int* in_sizes, int n_in,
                              void* d_out, int out_size)
{
    (void)in_sizes; (void)n_in; (void)out_size;
    const float* V     = (const float*)d_in[0];
    const float* C     = (const float*)d_in[1];
    const float* vn_g  = (const float*)d_in[2];
    const float* vn_b  = (const float*)d_in[3];
    const float* cn_g  = (const float*)d_in[4];
    const float* cn_b  = (const float*)d_in[5];
    const float* W_vqk = (const float*)d_in[6];
    const float* b_vqk = (const float*)d_in[7];
    const float* rms_v = (const float*)d_in[8];
    const float* W_cqk = (const float*)d_in[9];
    const float* b_cqk = (const float*)d_in[10];
    const float* rms_c = (const float*)d_in[11];
    const float* W_vv  = (const float*)d_in[12];
    const float* b_vv  = (const float*)d_in[13];
    const float* W_cv  = (const float*)d_in[14];
    const float* b_cv  = (const float*)d_in[15];
    const float* W_ov  = (const float*)d_in[16];
    const float* b_ov  = (const float*)d_in[17];
    const float* W_oc  = (const float*)d_in[18];
    const float* b_oc  = (const float*)d_in[19];

    float* out_v = (float*)d_out;
    float* out_c = out_v + (size_t)B_ * N_ * VD_;

    float* Sc = nullptr;
    cudaGetSymbolAddress((void**)&Sc, g_scratch);
    float* Vn  = Sc + OFF_VN;
    float* Cn  = Sc + OFF_CN;
    float* QKV = Sc + OFF_QKV;
    float* QKC = Sc + OFF_QKC;
    float* Vv  = Sc + OFF_VV;
    float* Vc  = Sc + OFF_VC;
    float* OV  = Sc + OFF_OV;
    float* OC  = Sc + OFF_OC;
    float* Smat = Sc + OFF_S;
    __half* Pb  = (__half*)(Sc + OFF_PB);
    __nv_bfloat16* Qhi = (__nv_bfloat16*)(Sc + OFF_QHI);
    __nv_bfloat16* Qlo = (__nv_bfloat16*)(Sc + OFF_QLO);
    __nv_bfloat16* Khi = (__nv_bfloat16*)(Sc + OFF_KHI);
    __nv_bfloat16* Klo = (__nv_bfloat16*)(Sc + OFF_KLO);
    __half* Vt  = (__half*)(Sc + OFF_VT);

    cudaFuncSetAttribute(scores_kernel, cudaFuncAttributeMaxDynamicSharedMemorySize, SC1_SMEM);
    cudaFuncSetAttribute(pv_kernel, cudaFuncAttributeMaxDynamicSharedMemorySize, SC2_SMEM);

    // 1. layernorms
    ln_kernel<<<ROWS_, VD_>>>(V, vn_g, vn_b, Vn, VD_);
    ln_kernel<<<ROWS_, CD_>>>(C, cn_g, cn_b, Cn, CD_);

    // 2. projections (fp32)
    gemm_bias<<<dim3(8, 128), 256>>>(Vn, W_vqk, b_vqk, QKV, ROWS_, 512, 256);
    gemm_bias<<<dim3(4, 128), 256>>>(Vn, W_vv,  b_vv,  Vv,  ROWS_, 256, 256);
    gemm_bias<<<dim3(8, 128), 256>>>(Cn, W_cqk, b_cqk, QKC, ROWS_, 512, 64);
    gemm_bias<<<dim3(4, 128), 256>>>(Cn, W_cv,  b_cv,  Vc,  ROWS_, 256, 64);

    // 3. rms norm + bf16 hi/lo split + head scatter (+ fp16 V transpose)
    rms_scatter<<<ROWS_, 256>>>(QKV, QKC, Vv, Vc, rms_v, rms_c, Qhi, Qlo, Khi, Klo, Vt);

    // 4. scores via mma.sync bf16 (compensated): S = (QhKh + QhKl + QlKh)/8
    scores_kernel<<<dim3(N_/128, N_/128, BH_), 256, SC1_SMEM>>>(Qhi, Qlo, Khi, Klo, Smat);

    // 5. softmax -> fp16 P
    softmax_kernel<<<BH_ * N_, 256>>>(Smat, Pb);

    // 6. O = P @ V via mma.sync fp16, scattered into OV/OC
    pv_kernel<<<dim3(N_/128, BH_), 256, SC2_SMEM>>>(Pb, Vt, OV, OC);

    // 7. output projections (fp32)
    gemm_bias<<<dim3(4, 128), 256>>>(OV, W_ov, b_ov, out_v, ROWS_, VD_, 256);
    gemm_bias<<<dim3(1, 128), 256>>>(OC, W_oc, b_oc, out_c, ROWS_, CD_, 256);
}

// round 16
// speedup vs baseline: 3.2917x; 1.0037x over previous
#include <cuda_runtime.h>
#include <cuda_bf16.h>
#include <cuda_fp16.h>
#include <math.h>
#include <stdint.h>

#define B_ 4
#define N_ 2048
#define VD_ 256
#define CD_ 64
#define H_ 4
#define ROWS_ (B_*N_)          // 8192
#define BH_ (B_*H_)            // 16

// ---------------- scratch (device global; no allocation) ----------------
#define OFF_VN    ((size_t)0)
#define OFF_CN    ((size_t)2097152)
#define OFF_QKV   ((size_t)2621440)
#define OFF_QKC   ((size_t)6815744)
#define OFF_VV    ((size_t)11010048)
#define OFF_VC    ((size_t)13107200)
#define OFF_OV    ((size_t)15204352)
#define OFF_OC    ((size_t)17301504)
#define OFF_QHI   ((size_t)19398656)   // 16*2048*128 fp16 each (2097152 floats)
#define OFF_QLO   ((size_t)21495808)
#define OFF_KHI   ((size_t)23592960)
#define OFF_KLO   ((size_t)25690112)
#define OFF_VT    ((size_t)27787264)
#define SCRATCH_FLOATS ((size_t)29884416)

__device__ __align__(1024) float g_scratch[SCRATCH_FLOATS];

// ================= warp MMA helpers (arch-agnostic: ldmatrix + mma.sync) =============
__device__ __forceinline__ uint32_t smem_u32(const void* p) {
    uint32_t a;
    asm("{ .reg .u64 t; cvta.to.shared.u64 t, %1; cvt.u32.u64 %0, t; }" : "=r"(a) : "l"(p));
    return a;
}
__device__ __forceinline__ void ldsm4(uint32_t& r0, uint32_t& r1, uint32_t& r2, uint32_t& r3,
                                      uint32_t addr) {
    asm volatile("ldmatrix.sync.aligned.m8n8.x4.shared.b16 {%0,%1,%2,%3}, [%4];"
                 : "=r"(r0), "=r"(r1), "=r"(r2), "=r"(r3) : "r"(addr));
}
__device__ __forceinline__ void mma_fp16(float* c, const uint32_t* a, const uint32_t* b) {
    asm volatile(
        "mma.sync.aligned.m16n8k16.row.col.f32.f16.f16.f32 "
        "{%0,%1,%2,%3}, {%4,%5,%6,%7}, {%8,%9}, {%0,%1,%2,%3};"
        : "+f"(c[0]), "+f"(c[1]), "+f"(c[2]), "+f"(c[3])
        : "r"(a[0]), "r"(a[1]), "r"(a[2]), "r"(a[3]), "r"(b[0]), "r"(b[1]));
}

// tile: 128 rows x 128 x 16-bit (256B/row), 16B chunks XOR-swizzled within the row
__device__ __forceinline__ uint32_t tile_off(int r, int c16) {
    return (uint32_t)(r * 256 + ((c16 ^ (r & 7)) << 4));
}
// 256-thread cooperative load of a [128 x 128] 16-bit tile (row stride in elements)
template <typename T>
__device__ __forceinline__ void load_tile(char* dst, const T* src, size_t stride, int tid) {
    #pragma unroll
    for (int it = 0; it < 8; it++) {
        int idx = tid + it * 256;
        int r = idx >> 4, c = idx & 15;
        uint4 v = *(const uint4*)(src + (size_t)r * stride + c * 8);
        *(uint4*)(dst + tile_off(r, c)) = v;
    }
}

// per-warp 16x128 score pass: cS[16][4] += A(16xk128 rows m0..) * B(128xk128)^T
__device__ __forceinline__ void score_pass(float (*cS)[4], uint32_t Abase, uint32_t Bbase,
                                           int m0, int lane) {
    const int j = lane & 7, g = lane >> 3;
    #pragma unroll
    for (int k = 0; k < 8; k++) {
        uint32_t a[4];
        ldsm4(a[0], a[1], a[2], a[3],
              Abase + tile_off(m0 + ((g & 1) ? 8 : 0) + j, k * 2 + (g >> 1)));
        uint32_t b[16][2];
        #pragma unroll
        for (int nb = 0; nb < 8; nb++) {
            ldsm4(b[nb * 2][0], b[nb * 2][1], b[nb * 2 + 1][0], b[nb * 2 + 1][1],
                  Bbase + tile_off(nb * 16 + (g >> 1) * 8 + j, k * 2 + (g & 1)));
        }
        #pragma unroll
        for (int ni = 0; ni < 16; ni++)
            mma_fp16(cS[ni], a, b[ni]);
    }
}

// ---------------- block reductions ----------------
__device__ __forceinline__ float block_sum(float v, float* red) {
    int lane = threadIdx.x & 31;
    #pragma unroll
    for (int o = 16; o; o >>= 1) v += __shfl_xor_sync(0xffffffffu, v, o);
    if (lane == 0) red[threadIdx.x >> 5] = v;
    __syncthreads();
    int nw = (blockDim.x + 31) >> 5;
    float r = (lane < nw) ? red[lane] : 0.f;
    #pragma unroll
    for (int o = 16; o; o >>= 1) r += __shfl_xor_sync(0xffffffffu, r, o);
    __syncthreads();
    return r;
}

// ---------------- layernorm ----------------
__global__ void ln_kernel(const float* __restrict__ x, const float* __restrict__ g,
                          const float* __restrict__ b, float* __restrict__ y, int dim)
{
    __shared__ float red[32];
    size_t row = blockIdx.x;
    float v = x[row * dim + threadIdx.x];
    float mean = block_sum(v, red) / (float)dim;
    float dv = v - mean;
    float var = block_sum(dv * dv, red) / (float)dim;
    y[row * dim + threadIdx.x] = dv * rsqrtf(var + 1e-5f) * g[threadIdx.x] + b[threadIdx.x];
}

// ---------------- fp32 GEMM (projections) ----------------
__global__ void gemm_bias(const float* __restrict__ A, const float* __restrict__ W,
                          const float* __restrict__ bias, float* __restrict__ Cm,
                          int M, int Nc, int K)
{
    __shared__ __align__(16) float As[16 * 68];
    __shared__ __align__(16) float Bs[16 * 64];
    const int tid = threadIdx.x;
    const int tx = tid & 15, ty = tid >> 4;
    const int m0 = blockIdx.y * 64;
    const int n0 = blockIdx.x * 64;
    float acc[4][4] = {};
    for (int k0 = 0; k0 < K; k0 += 16) {
        #pragma unroll
        for (int i = tid; i < 1024; i += 256) {
            int k = i & 15, m = i >> 4;
            As[k * 68 + m] = A[(size_t)(m0 + m) * K + k0 + k];
        }
        #pragma unroll
        for (int i = tid; i < 1024; i += 256) {
            int n = i & 63, k = i >> 6;
            Bs[k * 64 + n] = W[(size_t)(k0 + k) * Nc + n0 + n];
        }
        __syncthreads();
        #pragma unroll
        for (int k = 0; k < 16; k++) {
            float4 av = *(const float4*)&As[k * 68 + ty * 4];
            float4 bv = *(const float4*)&Bs[k * 64 + tx * 4];
            float a[4] = {av.x, av.y, av.z, av.w};
            float b4[4] = {bv.x, bv.y, bv.z, bv.w};
            #pragma unroll
            for (int ii = 0; ii < 4; ii++)
                #pragma unroll
                for (int jj = 0; jj < 4; jj++)
                    acc[ii][jj] += a[ii] * b4[jj];
        }
        __syncthreads();
    }
    #pragma unroll
    for (int ii = 0; ii < 4; ii++) {
        int m = m0 + ty * 4 + ii;
        int n = n0 + tx * 4;
        float4 out;
        out.x = acc[ii][0] + bias[n + 0];
        out.y = acc[ii][1] + bias[n + 1];
        out.z = acc[ii][2] + bias[n + 2];
        out.w = acc[ii][3] + bias[n + 3];
        *(float4*)&Cm[(size_t)m * Nc + n] = out;
    }
}

// ---------------- RMS norm + hi/lo fp16 split + head scatter ----------------
__device__ __forceinline__ void split_half(float x, __half& hi, __half& lo) {
    hi = __float2half(x);
    lo = __float2half(x - __half2float(hi));
}

__global__ void rms_scatter(const float* __restrict__ QKv, const float* __restrict__ QKc,
                            const float* __restrict__ Vv, const float* __restrict__ Vc,
                            const float* __restrict__ rms_v, const float* __restrict__ rms_c,
                            __half* __restrict__ Qhi, __half* __restrict__ Qlo,
                            __half* __restrict__ Khi, __half* __restrict__ Klo,
                            __half* __restrict__ Vt)
{
    __shared__ float red[32];
    int row = blockIdx.x;
    int b = row / N_, n = row % N_;
    int t = threadIdx.x;  // 256
    const float* qv = QKv + (size_t)row * 512;
    const float* qc = QKc + (size_t)row * 512;
    float sv = 0.f, sc = 0.f;
    #pragma unroll
    for (int i = t; i < 512; i += 256) { float a = qv[i]; sv += a * a; float c = qc[i]; sc += c * c; }
    sv = block_sum(sv, red);
    sc = block_sum(sc, red);
    float iv = rsqrtf(sv / 512.f + 1e-6f);
    float ic = rsqrtf(sc / 512.f + 1e-6f);
    int h = t >> 6, d = t & 63;
    int q = t;
    size_t bh = (size_t)(b * H_ + h);
    size_t qbase = (bh * N_ + n) * 128;

    float qV = qv[q] * iv * rms_v[q];
    float qC = qc[q] * ic * rms_c[q];
    float kV = qv[256 + q] * iv * rms_v[256 + q];
    float kC = qc[256 + q] * ic * rms_c[256 + q];

    __half hi, lo;
    split_half(qV, hi, lo); Qhi[qbase + d] = hi;      Qlo[qbase + d] = lo;
    split_half(qC, hi, lo); Qhi[qbase + 64 + d] = hi; Qlo[qbase + 64 + d] = lo;
    split_half(kV, hi, lo); Khi[qbase + d] = hi;      Klo[qbase + d] = lo;
    split_half(kC, hi, lo); Khi[qbase + 64 + d] = hi; Klo[qbase + 64 + d] = lo;

    // V transposed: Vt[bh][d][j], fp16
    Vt[(bh * 128 + d) * N_ + n]      = __float2half(Vv[(size_t)row * 256 + q]);
    Vt[(bh * 128 + 64 + d) * N_ + n] = __float2half(Vc[(size_t)row * 256 + q]);
}

// ---------------- fused flash attention ----------------
// grid (N/128, BH), 256 threads (8 warps x 16 rows). Compensated fp16 scores,
// online softmax, register-resident P -> fp16 PV. S and P never touch gmem.
#define FL_SMEM (5 * 32768)

__global__ void __launch_bounds__(256, 1)
flash_kernel(const __half* __restrict__ Qh, const __half* __restrict__ Ql,
             const __half* __restrict__ Kh, const __half* __restrict__ Kl,
             const __half* __restrict__ Vt,
             float* __restrict__ OV, float* __restrict__ OC)
{
    extern __shared__ __align__(16) char sm[];
    char* sQh = sm;
    char* sQl = sm + 32768;
    char* sKh = sm + 65536;
    char* sKl = sm + 98304;
    char* sV  = sm + 131072;

    const int tid = threadIdx.x, wid = tid >> 5, lane = tid & 31;
    const int it = blockIdx.x, bh = blockIdx.y;
    const size_t qoff = ((size_t)bh * N_ + it * 128) * 128;

    load_tile(sQh, Qh + qoff, 128, tid);
    load_tile(sQl, Ql + qoff, 128, tid);

    const int m0 = wid * 16;
    const int j = lane & 7, g = lane >> 3;

    float mrow0 = -3.0e38f, mrow1 = -3.0e38f;
    float lrow0 = 0.f, lrow1 = 0.f;
    float oacc[16][4];
    #pragma unroll
    for (int i = 0; i < 16; i++)
        #pragma unroll
        for (int x = 0; x < 4; x++) oacc[i][x] = 0.f;

    __syncthreads();

    const uint32_t uQh = smem_u32(sQh), uQl = smem_u32(sQl);
    const uint32_t uKh = smem_u32(sKh), uKl = smem_u32(sKl);
    const uint32_t uV  = smem_u32(sV);

    for (int ch = 0; ch < 16; ch++) {
        const size_t koff = ((size_t)bh * N_ + ch * 128) * 128;
        load_tile(sKh, Kh + koff, 128, tid);
        load_tile(sKl, Kl + koff, 128, tid);
        load_tile(sV, Vt + (size_t)bh * 128 * N_ + ch * 128, N_, tid);
        __syncthreads();

        float cS[16][4];
        #pragma unroll
        for (int i = 0; i < 16; i++)
            #pragma unroll
            for (int x = 0; x < 4; x++) cS[i][x] = 0.f;

        score_pass(cS, uQh, uKh, m0, lane);
        score_pass(cS, uQh, uKl, m0, lane);
        score_pass(cS, uQl, uKh, m0, lane);

        // scale + per-thread row maxima (rows qr and qr+8, 32 cols each)
        float mx0 = -3.0e38f, mx1 = -3.0e38f;
        #pragma unroll
        for (int ni = 0; ni < 16; ni++) {
            cS[ni][0] *= 0.125f; cS[ni][1] *= 0.125f;
            cS[ni][2] *= 0.125f; cS[ni][3] *= 0.125f;
            mx0 = fmaxf(mx0, fmaxf(cS[ni][0], cS[ni][1]));
            mx1 = fmaxf(mx1, fmaxf(cS[ni][2], cS[ni][3]));
        }
        mx0 = fmaxf(mx0, __shfl_xor_sync(0xffffffffu, mx0, 1));
        mx0 = fmaxf(mx0, __shfl_xor_sync(0xffffffffu, mx0, 2));
        mx1 = fmaxf(mx1, __shfl_xor_sync(0xffffffffu, mx1, 1));
        mx1 = fmaxf(mx1, __shfl_xor_sync(0xffffffffu, mx1, 2));

        float mn0 = fmaxf(mrow0, mx0), mn1 = fmaxf(mrow1, mx1);
        float al0 = __expf(mrow0 - mn0), al1 = __expf(mrow1 - mn1);
        mrow0 = mn0; mrow1 = mn1;

        // exp -> fp16 A fragments (register-direct), accumulate row sums
        float s0 = 0.f, s1 = 0.f;
        uint32_t aP[8][4];
        #pragma unroll
        for (int ni = 0; ni < 16; ni++) {
            float p0 = __expf(cS[ni][0] - mn0);
            float p1 = __expf(cS[ni][1] - mn0);
            float p2 = __expf(cS[ni][2] - mn1);
            float p3 = __expf(cS[ni][3] - mn1);
            s0 += p0 + p1; s1 += p2 + p3;
            __half2 h01 = __float22half2_rn(make_float2(p0, p1));
            __half2 h23 = __float22half2_rn(make_float2(p2, p3));
            aP[ni >> 1][(ni & 1) * 2 + 0] = *(uint32_t*)&h01;
            aP[ni >> 1][(ni & 1) * 2 + 1] = *(uint32_t*)&h23;
        }
        s0 += __shfl_xor_sync(0xffffffffu, s0, 1);
        s0 += __shfl_xor_sync(0xffffffffu, s0, 2);
        s1 += __shfl_xor_sync(0xffffffffu, s1, 1);
        s1 += __shfl_xor_sync(0xffffffffu, s1, 2);
        lrow0 = lrow0 * al0 + s0;
        lrow1 = lrow1 * al1 + s1;

        // rescale O accumulator
        #pragma unroll
        for (int nd = 0; nd < 16; nd++) {
            oacc[nd][0] *= al0; oacc[nd][1] *= al0;
            oacc[nd][2] *= al1; oacc[nd][3] *= al1;
        }

        // PV: O += P(16 x j128) * V(j128 x d128)
        #pragma unroll
        for (int kc = 0; kc < 8; kc++) {
            uint32_t b[16][2];
            #pragma unroll
            for (int nb = 0; nb < 8; nb++) {
                ldsm4(b[nb * 2][0], b[nb * 2][1], b[nb * 2 + 1][0], b[nb * 2 + 1][1],
                      uV + tile_off(nb * 16 + (g >> 1) * 8 + j, kc * 2 + (g & 1)));
            }
            #pragma unroll
            for (int nd = 0; nd < 16; nd++)
                mma_fp16(oacc[nd], aP[kc], b[nd]);
        }
        __syncthreads();
    }

    // epilogue: normalize + scatter into OV/OC pre-projection layout
    const int qr = lane >> 2, qc2 = (lane & 3) * 2;
    const int bb = bh >> 2, h = bh & 3;
    const float inv0 = 1.f / lrow0, inv1 = 1.f / lrow1;
    const int r0 = it * 128 + m0 + qr;
    #pragma unroll
    for (int nd = 0; nd < 16; nd++) {
        int d = nd * 8 + qc2;
        float* dst = (d < 64) ? OV : OC;
        int dc = d & 63;
        size_t a1 = ((size_t)bb * N_ + r0) * 256 + h * 64 + dc;
        size_t a2 = ((size_t)bb * N_ + r0 + 8) * 256 + h * 64 + dc;
        *(float2*)(dst + a1) = make_float2(oacc[nd][0] * inv0, oacc[nd][1] * inv0);
        *(float2*)(dst + a2) = make_float2(oacc[nd][2] * inv1, oacc[nd][3] * inv1);
    }
}

// ---------------- launch ----------------
extern "C" void kernel_launch(void* const* d_in, const int* in_sizes, int n_in,
                              void* d_out, int out_size)
{
    (void)in_sizes; (void)n_in; (void)out_size;
    const float* V     = (const float*)d_in[0];
    const float* C     = (const float*)d_in[1];
    const float* vn_g  = (const float*)d_in[2];
    const float* vn_b  = (const float*)d_in[3];
    const float* cn_g  = (const float*)d_in[4];
    const float* cn_b  = (const float*)d_in[5];
    const float* W_vqk = (const float*)d_in[6];
    const float* b_vqk = (const float*)d_in[7];
    const float* rms_v = (const float*)d_in[8];
    const float* W_cqk = (const float*)d_in[9];
    const float* b_cqk = (const float*)d_in[10];
    const float* rms_c = (const float*)d_in[11];
    const float* W_vv  = (const float*)d_in[12];
    const float* b_vv  = (const float*)d_in[13];
    const float* W_cv  = (const float*)d_in[14];
    const float* b_cv  = (const float*)d_in[15];
    const float* W_ov  = (const float*)d_in[16];
    const float* b_ov  = (const float*)d_in[17];
    const float* W_oc  = (const float*)d_in[18];
    const float* b_oc  = (const float*)d_in[19];

    float* out_v = (float*)d_out;
    float* out_c = out_v + (size_t)B_ * N_ * VD_;

    float* Sc = nullptr;
    cudaGetSymbolAddress((void**)&Sc, g_scratch);
    float* Vn  = Sc + OFF_VN;
    float* Cn  = Sc + OFF_CN;
    float* QKV = Sc + OFF_QKV;
    float* QKC = Sc + OFF_QKC;
    float* Vv  = Sc + OFF_VV;
    float* Vc  = Sc + OFF_VC;
    float* OV  = Sc + OFF_OV;
    float* OC  = Sc + OFF_OC;
    __half* Qhi = (__half*)(Sc + OFF_QHI);
    __half* Qlo = (__half*)(Sc + OFF_QLO);
    __half* Khi = (__half*)(Sc + OFF_KHI);
    __half* Klo = (__half*)(Sc + OFF_KLO);
    __half* Vt  = (__half*)(Sc + OFF_VT);

    cudaFuncSetAttribute(flash_kernel, cudaFuncAttributeMaxDynamicSharedMemorySize, FL_SMEM);

    // 1. layernorms
    ln_kernel<<<ROWS_, VD_>>>(V, vn_g, vn_b, Vn, VD_);
    ln_kernel<<<ROWS_, CD_>>>(C, cn_g, cn_b, Cn, CD_);

    // 2. projections (fp32)
    gemm_bias<<<dim3(8, 128), 256>>>(Vn, W_vqk, b_vqk, QKV, ROWS_, 512, 256);
    gemm_bias<<<dim3(4, 128), 256>>>(Vn, W_vv,  b_vv,  Vv,  ROWS_, 256, 256);
    gemm_bias<<<dim3(8, 128), 256>>>(Cn, W_cqk, b_cqk, QKC, ROWS_, 512, 64);
    gemm_bias<<<dim3(4, 128), 256>>>(Cn, W_cv,  b_cv,  Vc,  ROWS_, 256, 64);

    // 3. rms norm + fp16 hi/lo split + head scatter (+ fp16 V transpose)
    rms_scatter<<<ROWS_, 256>>>(QKV, QKC, Vv, Vc, rms_v, rms_c, Qhi, Qlo, Khi, Klo, Vt);

    // 4. fused flash attention (compensated fp16 scores, online softmax, fp16 PV)
    flash_kernel<<<dim3(N_/128, BH_), 256, FL_SMEM>>>(Qhi, Qlo, Khi, Klo, Vt, OV, OC);

    // 5. output projections (fp32)
    gemm_bias<<<dim3(4, 128), 256>>>(OV, W_ov, b_ov, out_v, ROWS_, VD_, 256);
    gemm_bias<<<dim3(1, 128), 256>>>(OC, W_oc, b_oc, out_c, ROWS_, CD_, 256);
}